// round 12
// baseline (speedup 1.0000x reference)
#include <cuda_runtime.h>
#include <cuda_fp16.h>
#include <cstdint>

#define NB_CAT    8192
#define RANK      16
#define N_COLS    4
#define N_GRP     8              // (col, rank-half)
#define MAX_PAIRS 1048576
#define CTA_PER_GRP 18
#define GATHER_CTAS (N_GRP * CTA_PER_GRP)   // 144

// R12: SMEM-crossbar gather, v2. Table split into 8 slices of 128KB
// (grp = col*2 + rankhalf, rows = 16B). Each CTA owns one slice in SMEM and
// a static 1/18 share of the pairs. Indices pre-transposed to xT[c][p] for
// coalesced scalar loads; 2 pairs/thread/iter with one-iteration prefetch.
// Partials -> static scratch; combine kernel sums 8 partials (deterministic).

__device__ __half2 g_cfr[N_GRP * NB_CAT * 4];          // 1 MB: [grp][cat][16B]
__device__ int     g_xT[N_COLS * MAX_PAIRS];            // 16 MB
__device__ int     g_yT[N_COLS * MAX_PAIRS];            // 16 MB
__device__ float   g_part[(size_t)N_GRP * MAX_PAIRS];   // 32 MB

// --- K1: convert fp32 cf[c][cat][r] -> fp16 slices [grp][cat][8 halves] ---
__global__ __launch_bounds__(256) void convert_kernel(const float* __restrict__ cf)
{
    const int j = blockIdx.x * blockDim.x + threadIdx.x;   // uint4 out index
    const int n = N_GRP * NB_CAT;                          // 65536
    if (j < n) {
        const int grp  = j >> 13;
        const int cat  = j & (NB_CAT - 1);
        const int c    = grp >> 1;
        const int half = grp & 1;
        const float4 v0 = __ldcg((const float4*)(cf + ((size_t)(c * NB_CAT + cat) * RANK + half * 8)));
        const float4 v1 = __ldcg((const float4*)(cf + ((size_t)(c * NB_CAT + cat) * RANK + half * 8 + 4)));
        uint4 o;
        *(__half2*)&o.x = __float22half2_rn(make_float2(v0.x, v0.y));
        *(__half2*)&o.y = __float22half2_rn(make_float2(v0.z, v0.w));
        *(__half2*)&o.z = __float22half2_rn(make_float2(v1.x, v1.y));
        *(__half2*)&o.w = __float22half2_rn(make_float2(v1.z, v1.w));
        ((uint4*)g_cfr)[j] = o;
    }
}

// --- K2: transpose indices: x[p][c] -> xT[c][p] (all loads/stores coalesced) ---
__global__ __launch_bounds__(256) void transpose_idx_kernel(
    const int* __restrict__ x, const int* __restrict__ y, int n_pairs)
{
    const int p = blockIdx.x * blockDim.x + threadIdx.x;
    if (p < n_pairs) {
        const int4 xv = __ldcg((const int4*)x + p);
        const int4 yv = __ldcg((const int4*)y + p);
        g_xT[0 * MAX_PAIRS + p] = xv.x;  g_xT[1 * MAX_PAIRS + p] = xv.y;
        g_xT[2 * MAX_PAIRS + p] = xv.z;  g_xT[3 * MAX_PAIRS + p] = xv.w;
        g_yT[0 * MAX_PAIRS + p] = yv.x;  g_yT[1 * MAX_PAIRS + p] = yv.y;
        g_yT[2 * MAX_PAIRS + p] = yv.z;  g_yT[3 * MAX_PAIRS + p] = yv.w;
    }
}

__device__ __forceinline__ float dot16B(const uint4& a, const uint4& b)
{
    __half2 s = __hmul2(*(const __half2*)&a.x, *(const __half2*)&b.x);
    s = __hfma2(*(const __half2*)&a.y, *(const __half2*)&b.y, s);
    s = __hfma2(*(const __half2*)&a.z, *(const __half2*)&b.z, s);
    s = __hfma2(*(const __half2*)&a.w, *(const __half2*)&b.w, s);
    const float2 f = __half22float2(s);
    return f.x + f.y;
}

// --- K3: slice-resident gather. 144 CTAs x 1024 thr, 128KB dyn smem. ---
__global__ __launch_bounds__(1024, 1) void gather_kernel(
    const float* __restrict__ stdv,   // [N_COLS, NB_CAT]
    int n_pairs)
{
    extern __shared__ __align__(16) uint4 sm[];   // 8192 rows x 16B = 128KB

    const int grp    = blockIdx.x & (N_GRP - 1);
    const int member = blockIdx.x >> 3;           // 0..17
    const int col    = grp >> 1;
    const int half   = grp & 1;

    // Stage this group's 128KB slice (dense, coalesced)
    {
        const uint4* src = (const uint4*)g_cfr + (size_t)grp * NB_CAT;
        #pragma unroll
        for (int i = 0; i < NB_CAT / 1024; i++)
            sm[i * 1024 + threadIdx.x] = src[i * 1024 + threadIdx.x];
    }
    __syncthreads();

    const int start = (int)((long long)member * n_pairs / CTA_PER_GRP);
    const int end   = (int)((long long)(member + 1) * n_pairs / CTA_PER_GRP);

    const int*   xT = g_xT + (size_t)col * MAX_PAIRS;
    const int*   yT = g_yT + (size_t)col * MAX_PAIRS;
    const float* sc = stdv + (size_t)col * NB_CAT;
    float* part = g_part + (size_t)grp * MAX_PAIRS;

    // 2 pairs per thread per iteration, one-iteration index prefetch
    int p0 = start + (int)threadIdx.x;
    int p1 = p0 + 1024;

    int xi0 = 0, yi0 = 0, xi1 = 0, yi1 = 0;
    if (p0 < end) { xi0 = __ldcg(xT + p0); yi0 = __ldcg(yT + p0); }
    if (p1 < end) { xi1 = __ldcg(xT + p1); yi1 = __ldcg(yT + p1); }

    while (p0 < end) {
        const int n0 = p0 + 2048, n1 = p1 + 2048;

        // LDS gathers (issued back-to-back; rows are 16B in a 128KB slice)
        const uint4 a0 = sm[xi0], b0 = sm[yi0];
        uint4 a1, b1;
        const bool has1 = (p1 < end);
        if (has1) { a1 = sm[xi1]; b1 = sm[yi1]; }

        // Prefetch next iteration's indices
        int nx0 = 0, ny0 = 0, nx1 = 0, ny1 = 0;
        if (n0 < end) { nx0 = __ldcg(xT + n0); ny0 = __ldcg(yT + n0); }
        if (n1 < end) { nx1 = __ldcg(xT + n1); ny1 = __ldcg(yT + n1); }

        // Math + rare diagonal (added once per (pair,col): half==0 groups only)
        float acc0 = dot16B(a0, b0);
        if (half == 0 && xi0 == yi0) { const float s = sc[xi0]; acc0 += s * s; }
        part[p0] = acc0;

        if (has1) {
            float acc1 = dot16B(a1, b1);
            if (half == 0 && xi1 == yi1) { const float s = sc[xi1]; acc1 += s * s; }
            part[p1] = acc1;
        }

        p0 = n0; p1 = n1;
        xi0 = nx0; yi0 = ny0; xi1 = nx1; yi1 = ny1;
    }
}

// --- K4: out[p] = sum of 8 group partials (fixed order -> deterministic) ---
__global__ __launch_bounds__(256) void combine_kernel(float* __restrict__ out, int n_pairs)
{
    const int i = blockIdx.x * blockDim.x + threadIdx.x;   // float4 index
    const int n4 = n_pairs >> 2;
    if (i < n4) {
        float4 s = make_float4(0.f, 0.f, 0.f, 0.f);
        #pragma unroll
        for (int g = 0; g < N_GRP; g++) {
            const float4 v = __ldcg((const float4*)(g_part + (size_t)g * MAX_PAIRS) + i);
            s.x += v.x; s.y += v.y; s.z += v.z; s.w += v.w;
        }
        ((float4*)out)[i] = s;
    }
}

extern "C" void kernel_launch(void* const* d_in, const int* in_sizes, int n_in,
                              void* d_out, int out_size)
{
    const int*   x    = (const int*)d_in[0];
    const int*   y    = (const int*)d_in[1];
    const float* cf   = (const float*)d_in[2];
    const float* stdv = (const float*)d_in[3];
    float*       out  = (float*)d_out;

    const int n_pairs = out_size;  // 1048576

    static bool attr_set = false;
    if (!attr_set) {
        cudaFuncSetAttribute(gather_kernel,
                             cudaFuncAttributeMaxDynamicSharedMemorySize,
                             NB_CAT * 16);
        attr_set = true;
    }

    {   // K1: table convert+reshape (65536 uint4)
        const int n = N_GRP * NB_CAT;
        convert_kernel<<<(n + 255) / 256, 256>>>(cf);
    }
    {   // K2: index transpose
        transpose_idx_kernel<<<(n_pairs + 255) / 256, 256>>>(x, y, n_pairs);
    }
    // K3: slice-resident gather (1 CTA/SM by smem footprint)
    gather_kernel<<<GATHER_CTAS, 1024, NB_CAT * 16>>>(stdv, n_pairs);
    {   // K4: combine
        const int n4 = n_pairs >> 2;
        combine_kernel<<<(n4 + 255) / 256, 256>>>(out, n_pairs);
    }
}

// round 13
// speedup vs baseline: 1.1617x; 1.1617x over previous
#include <cuda_runtime.h>
#include <cuda_fp16.h>
#include <cstdint>

#define NB_CAT    8192
#define RANK      16
#define N_COLS    4
#define N_GRP     8              // (col, rank-half)
#define MAX_PAIRS 1048576
#define CTA_PER_GRP 18
#define GATHER_CTAS (N_GRP * CTA_PER_GRP)   // 144

// R13: SMEM-crossbar pipeline v3.
//  - packed uint indices (x<<16|y): transpose writes 16MB; gather reads one
//    uint4 per 4 pairs (coalesced).
//  - fp16 partials: combine traffic 36MB -> 20MB.
//  - gather: 4 pairs/thread/iter -> 8 back-to-back LDS.128 (256 random 16B
//    rows per warp-iter) keeps the 128B/cyc crossbar continuously fed;
//    4-aligned CTA ranges keep the hot loop branch-light.

__device__ __half2  g_cfr[N_GRP * NB_CAT * 4];           // 1 MB: [grp][cat][16B]
__device__ unsigned g_xyT[N_COLS * MAX_PAIRS];            // 16 MB packed (x<<16|y)
__device__ __half   g_parth[(size_t)N_GRP * MAX_PAIRS];   // 16 MB partials

// --- K1: convert fp32 cf[c][cat][r] -> fp16 slices [grp][cat][8 halves] ---
__global__ __launch_bounds__(256) void convert_kernel(const float* __restrict__ cf)
{
    const int j = blockIdx.x * blockDim.x + threadIdx.x;   // uint4 out index
    const int n = N_GRP * NB_CAT;                          // 65536
    if (j < n) {
        const int grp  = j >> 13;
        const int cat  = j & (NB_CAT - 1);
        const int c    = grp >> 1;
        const int half = grp & 1;
        const float4 v0 = __ldcg((const float4*)(cf + ((size_t)(c * NB_CAT + cat) * RANK + half * 8)));
        const float4 v1 = __ldcg((const float4*)(cf + ((size_t)(c * NB_CAT + cat) * RANK + half * 8 + 4)));
        uint4 o;
        *(__half2*)&o.x = __float22half2_rn(make_float2(v0.x, v0.y));
        *(__half2*)&o.y = __float22half2_rn(make_float2(v0.z, v0.w));
        *(__half2*)&o.z = __float22half2_rn(make_float2(v1.x, v1.y));
        *(__half2*)&o.w = __float22half2_rn(make_float2(v1.z, v1.w));
        ((uint4*)g_cfr)[j] = o;
    }
}

// --- K2: pack+transpose indices: xyT[c][p] = (x[p][c]<<16) | y[p][c] ---
__global__ __launch_bounds__(256) void transpose_idx_kernel(
    const int* __restrict__ x, const int* __restrict__ y, int n_pairs)
{
    const int p = blockIdx.x * blockDim.x + threadIdx.x;
    if (p < n_pairs) {
        const int4 xv = __ldcg((const int4*)x + p);
        const int4 yv = __ldcg((const int4*)y + p);
        g_xyT[0 * MAX_PAIRS + p] = ((unsigned)xv.x << 16) | (unsigned)yv.x;
        g_xyT[1 * MAX_PAIRS + p] = ((unsigned)xv.y << 16) | (unsigned)yv.y;
        g_xyT[2 * MAX_PAIRS + p] = ((unsigned)xv.z << 16) | (unsigned)yv.z;
        g_xyT[3 * MAX_PAIRS + p] = ((unsigned)xv.w << 16) | (unsigned)yv.w;
    }
}

__device__ __forceinline__ float dot16B(const uint4& a, const uint4& b)
{
    __half2 s = __hmul2(*(const __half2*)&a.x, *(const __half2*)&b.x);
    s = __hfma2(*(const __half2*)&a.y, *(const __half2*)&b.y, s);
    s = __hfma2(*(const __half2*)&a.z, *(const __half2*)&b.z, s);
    s = __hfma2(*(const __half2*)&a.w, *(const __half2*)&b.w, s);
    const float2 f = __half22float2(s);
    return f.x + f.y;
}

// --- K3: slice-resident gather. 144 CTAs x 1024 thr, 128KB dyn smem. ---
__global__ __launch_bounds__(1024, 1) void gather_kernel(
    const float* __restrict__ stdv,   // [N_COLS, NB_CAT]
    int n_pairs)
{
    extern __shared__ __align__(16) uint4 sm[];   // 8192 rows x 16B = 128KB

    const int grp    = blockIdx.x & (N_GRP - 1);
    const int member = blockIdx.x >> 3;           // 0..17
    const int col    = grp >> 1;
    const int half   = grp & 1;

    // Stage this group's 128KB slice (dense, coalesced)
    {
        const uint4* src = (const uint4*)g_cfr + (size_t)grp * NB_CAT;
        #pragma unroll
        for (int i = 0; i < NB_CAT / 1024; i++)
            sm[i * 1024 + threadIdx.x] = src[i * 1024 + threadIdx.x];
    }
    __syncthreads();

    // 4-aligned range boundaries (n_pairs itself is a multiple of 4)
    const int start = (int)(((long long)member * n_pairs / CTA_PER_GRP) & ~3LL);
    const int end   = (member == CTA_PER_GRP - 1)
                      ? n_pairs
                      : (int)(((long long)(member + 1) * n_pairs / CTA_PER_GRP) & ~3LL);

    const unsigned* xy = g_xyT + (size_t)col * MAX_PAIRS;
    const float*    sc = stdv + (size_t)col * NB_CAT;
    __half*       part = g_parth + (size_t)grp * MAX_PAIRS;

    for (int p4 = start + (int)threadIdx.x * 4; p4 < end; p4 += 4096) {
        if (p4 + 4 <= end) {
            // ---- 1 coalesced idx load = 4 packed pairs ----
            const uint4 q = *(const uint4*)(xy + p4);
            const unsigned x0 = q.x >> 16, y0 = q.x & 0xffffu;
            const unsigned x1 = q.y >> 16, y1 = q.y & 0xffffu;
            const unsigned x2 = q.z >> 16, y2 = q.z & 0xffffu;
            const unsigned x3 = q.w >> 16, y3 = q.w & 0xffffu;

            // ---- 8 back-to-back LDS.128 (256 rows per warp-iter) ----
            const uint4 a0 = sm[x0], b0 = sm[y0];
            const uint4 a1 = sm[x1], b1 = sm[y1];
            const uint4 a2 = sm[x2], b2 = sm[y2];
            const uint4 a3 = sm[x3], b3 = sm[y3];

            float f0 = dot16B(a0, b0);
            float f1 = dot16B(a1, b1);
            float f2 = dot16B(a2, b2);
            float f3 = dot16B(a3, b3);

            // diag added once per (pair,col): half==0 group only (rare)
            if (half == 0) {
                if (x0 == y0) { const float s = sc[x0]; f0 += s * s; }
                if (x1 == y1) { const float s = sc[x1]; f1 += s * s; }
                if (x2 == y2) { const float s = sc[x2]; f2 += s * s; }
                if (x3 == y3) { const float s = sc[x3]; f3 += s * s; }
            }

            // ---- pack 4 fp16 partials -> 8B coalesced store ----
            const __half2 h01 = __floats2half2_rn(f0, f1);
            const __half2 h23 = __floats2half2_rn(f2, f3);
            uint2 o;
            o.x = *(const unsigned*)&h01;
            o.y = *(const unsigned*)&h23;
            *(uint2*)(part + p4) = o;
        } else {
            // scalar tail (only at the very last range edge)
            for (int p = p4; p < end; p++) {
                const unsigned q = xy[p];
                const unsigned xp = q >> 16, yp = q & 0xffffu;
                float f = dot16B(sm[xp], sm[yp]);
                if (half == 0 && xp == yp) { const float s = sc[xp]; f += s * s; }
                part[p] = __float2half_rn(f);
            }
        }
    }
}

// --- K4: out[p] = sum of 8 fp16 group partials (fixed order, deterministic) ---
__global__ __launch_bounds__(256) void combine_kernel(float* __restrict__ out, int n_pairs)
{
    const int i = blockIdx.x * blockDim.x + threadIdx.x;   // 4-pair block
    const int n4 = n_pairs >> 2;
    if (i < n4) {
        float4 s = make_float4(0.f, 0.f, 0.f, 0.f);
        #pragma unroll
        for (int g = 0; g < N_GRP; g++) {
            const uint2 v = __ldcg((const uint2*)(g_parth + (size_t)g * MAX_PAIRS) + i);
            const float2 lo = __half22float2(*(const __half2*)&v.x);
            const float2 hi = __half22float2(*(const __half2*)&v.y);
            s.x += lo.x; s.y += lo.y; s.z += hi.x; s.w += hi.y;
        }
        ((float4*)out)[i] = s;
    }
}

extern "C" void kernel_launch(void* const* d_in, const int* in_sizes, int n_in,
                              void* d_out, int out_size)
{
    const int*   x    = (const int*)d_in[0];
    const int*   y    = (const int*)d_in[1];
    const float* cf   = (const float*)d_in[2];
    const float* stdv = (const float*)d_in[3];
    float*       out  = (float*)d_out;

    const int n_pairs = out_size;  // 1048576

    static bool attr_set = false;
    if (!attr_set) {
        cudaFuncSetAttribute(gather_kernel,
                             cudaFuncAttributeMaxDynamicSharedMemorySize,
                             NB_CAT * 16);
        attr_set = true;
    }

    {   // K1: table convert+reshape
        const int n = N_GRP * NB_CAT;
        convert_kernel<<<(n + 255) / 256, 256>>>(cf);
    }
    {   // K2: index pack+transpose
        transpose_idx_kernel<<<(n_pairs + 255) / 256, 256>>>(x, y, n_pairs);
    }
    // K3: slice-resident gather
    gather_kernel<<<GATHER_CTAS, 1024, NB_CAT * 16>>>(stdv, n_pairs);
    {   // K4: combine
        const int n4 = n_pairs >> 2;
        combine_kernel<<<(n4 + 255) / 256, 256>>>(out, n_pairs);
    }
}

// round 14
// speedup vs baseline: 1.2731x; 1.0959x over previous
#include <cuda_runtime.h>
#include <cuda_fp16.h>
#include <cstdint>

#define NB_CAT  8192
#define RANK    16
#define N_COLS  4

// R14 = R10 (champion) with ONE substantive change: table gathers use __ldcg
// (L1-bypass). Model: with .ca, ~78% of the 8M row-gathers miss L1 and each
// miss's 32B sector fill steals L1 data-path cycles (0.78*0.25*8M ~= 1.56M
// wf-cycles = the measured gap to the 1-wf/cyc floor). .cg skips allocation,
// trading (useless, 22%-hit) L1 caching for a clean data path. L2 traffic
// rises to 256MB over ~31us ~= 8.5TB/s, under the ~12TB/s LTS cap.
// Also: request max-L1 carveout, streaming stores for out.

__device__ __half2 g_cfh[N_COLS * NB_CAT * RANK / 2];   // 4 MB, layout = cf

__global__ __launch_bounds__(256) void convert_cf_kernel(const float* __restrict__ cf)
{
    const int i = blockIdx.x * blockDim.x + threadIdx.x;   // uint4 (=8 halves) index
    const int n = N_COLS * NB_CAT * RANK / 8;              // 262,144
    if (i < n) {
        const float4 v0 = __ldcg((const float4*)cf + i * 2);
        const float4 v1 = __ldcg((const float4*)cf + i * 2 + 1);
        uint4 o;
        *(__half2*)&o.x = __float22half2_rn(make_float2(v0.x, v0.y));
        *(__half2*)&o.y = __float22half2_rn(make_float2(v0.z, v0.w));
        *(__half2*)&o.z = __float22half2_rn(make_float2(v1.x, v1.y));
        *(__half2*)&o.w = __float22half2_rn(make_float2(v1.z, v1.w));
        ((uint4*)g_cfh)[i] = o;
    }
}

__global__ __launch_bounds__(256, 6) void pair_cov_kernel(
    const int*   __restrict__ x,
    const int*   __restrict__ y,
    const float* __restrict__ stdv,   // [N_COLS, NB_CAT]
    float*       __restrict__ out,
    int n_pairs)
{
    const int lane = threadIdx.x & 31;
    const int sub  = lane & 3;        // 8B chunk of the 32B fp16 row
    const int unit = lane >> 2;       // pair slot (0..7) within warp-iter

    const int warp_global = (int)((blockIdx.x * blockDim.x + threadIdx.x) >> 5);
    const int nwarps      = (int)((gridDim.x * blockDim.x) >> 5);

    const uint2* cfh = (const uint2*)g_cfh;   // row r -> cfh[r*4 + sub]

    int base = warp_global * 8;
    if (base >= n_pairs) return;

    // Prime the index pipeline
    int4 xi = __ldcg((const int4*)x + base + unit);
    int4 yi = __ldcg((const int4*)y + base + unit);

    while (base < n_pairs) {
        const int nbase = base + nwarps * 8;

        // ---- Issue all 8 row gathers back-to-back (MLP = 8), L1-bypass ----
        uint2 av0 = __ldcg(cfh + (size_t)(0 * NB_CAT + xi.x) * 4 + sub);
        uint2 bv0 = __ldcg(cfh + (size_t)(0 * NB_CAT + yi.x) * 4 + sub);
        uint2 av1 = __ldcg(cfh + (size_t)(1 * NB_CAT + xi.y) * 4 + sub);
        uint2 bv1 = __ldcg(cfh + (size_t)(1 * NB_CAT + yi.y) * 4 + sub);
        uint2 av2 = __ldcg(cfh + (size_t)(2 * NB_CAT + xi.z) * 4 + sub);
        uint2 bv2 = __ldcg(cfh + (size_t)(2 * NB_CAT + yi.z) * 4 + sub);
        uint2 av3 = __ldcg(cfh + (size_t)(3 * NB_CAT + xi.w) * 4 + sub);
        uint2 bv3 = __ldcg(cfh + (size_t)(3 * NB_CAT + yi.w) * 4 + sub);

        // ---- Diagonal term while gathers fly (fp32 std, exact) ----
        float acc = 0.0f;
        {
            const int xd = (sub == 0) ? xi.x : (sub == 1) ? xi.y : (sub == 2) ? xi.z : xi.w;
            const int yd = (sub == 0) ? yi.x : (sub == 1) ? yi.y : (sub == 2) ? yi.z : yi.w;
            if (xd == yd) {
                const float s = stdv[sub * NB_CAT + xd];
                acc = s * s;
            }
        }

        // ---- Prefetch next iteration's indices ----
        int4 nxi, nyi;
        if (nbase < n_pairs) {
            nxi = __ldcg((const int4*)x + nbase + unit);
            nyi = __ldcg((const int4*)y + nbase + unit);
        }
        xi = nxi;
        yi = nyi;

        // ---- Math: per-column dot in half2, fp32 cross-column accumulate ----
        __half2 p0 = __hmul2(*(const __half2*)&av0.x, *(const __half2*)&bv0.x);
        p0 = __hfma2(*(const __half2*)&av0.y, *(const __half2*)&bv0.y, p0);
        __half2 p1 = __hmul2(*(const __half2*)&av1.x, *(const __half2*)&bv1.x);
        p1 = __hfma2(*(const __half2*)&av1.y, *(const __half2*)&bv1.y, p1);
        __half2 p2 = __hmul2(*(const __half2*)&av2.x, *(const __half2*)&bv2.x);
        p2 = __hfma2(*(const __half2*)&av2.y, *(const __half2*)&bv2.y, p2);
        __half2 p3 = __hmul2(*(const __half2*)&av3.x, *(const __half2*)&bv3.x);
        p3 = __hfma2(*(const __half2*)&av3.y, *(const __half2*)&bv3.y, p3);

        const float2 f0 = __half22float2(p0);
        const float2 f1 = __half22float2(p1);
        const float2 f2 = __half22float2(p2);
        const float2 f3 = __half22float2(p3);
        acc += (f0.x + f0.y) + (f1.x + f1.y);
        acc += (f2.x + f2.y) + (f3.x + f3.y);

        // ---- Reduce over the 4 chunk lanes; lane 0 of each unit writes ----
        acc += __shfl_xor_sync(0xffffffffu, acc, 1);
        acc += __shfl_xor_sync(0xffffffffu, acc, 2);

        if (sub == 0) {
            __stcs(out + base + unit, acc);   // streaming store, 1 wf per warp
        }

        base = nbase;
    }
}

extern "C" void kernel_launch(void* const* d_in, const int* in_sizes, int n_in,
                              void* d_out, int out_size)
{
    const int*   x    = (const int*)d_in[0];
    const int*   y    = (const int*)d_in[1];
    const float* cf   = (const float*)d_in[2];
    const float* stdv = (const float*)d_in[3];
    float*       out  = (float*)d_out;

    const int n_pairs = out_size;  // 1048576

    // Max-L1 carveout (0% shared) — harmless under .cg, helps if driver
    // defaults lower. Host-side attribute, no allocation, no guard.
    cudaFuncSetAttribute(pair_cov_kernel,
                         cudaFuncAttributePreferredSharedMemoryCarveout, 0);

    // 1) Convert covar_factor fp32 -> fp16 (vectorized)
    {
        const int n = N_COLS * NB_CAT * RANK / 8;
        convert_cf_kernel<<<(n + 255) / 256, 256>>>(cf);
    }

    // 2) Main gather kernel: single resident wave at 6 blocks/SM
    {
        const int threads = 256;
        const int blocks  = 148 * 6;
        pair_cov_kernel<<<blocks, threads>>>(x, y, stdv, out, n_pairs);
    }
}

// round 15
// speedup vs baseline: 1.3312x; 1.0457x over previous
#include <cuda_runtime.h>
#include <cuda_fp16.h>
#include <cstdint>

#define NB_CAT  8192
#define RANK    16
#define N_COLS  4

// R15 = R10 champion (occ 6, batch-8 MLP, half2 math, .ca table loads,
// vectorized convert) + PreferredSharedMemoryCarveout = 0% shared (max L1D).
// R14 proved L1 allocation is net-positive (.cg bypass regressed 35.3->39.1),
// so maximizing the L1D carveout is the remaining lever on the ~16% fill tax
// above the 1-wf/cyc L1tex floor.

__device__ __half2 g_cfh[N_COLS * NB_CAT * RANK / 2];   // 4 MB, layout = cf

__global__ __launch_bounds__(256) void convert_cf_kernel(const float* __restrict__ cf)
{
    const int i = blockIdx.x * blockDim.x + threadIdx.x;   // uint4 (=8 halves) index
    const int n = N_COLS * NB_CAT * RANK / 8;              // 262,144
    if (i < n) {
        const float4 v0 = __ldcg((const float4*)cf + i * 2);
        const float4 v1 = __ldcg((const float4*)cf + i * 2 + 1);
        uint4 o;
        *(__half2*)&o.x = __float22half2_rn(make_float2(v0.x, v0.y));
        *(__half2*)&o.y = __float22half2_rn(make_float2(v0.z, v0.w));
        *(__half2*)&o.z = __float22half2_rn(make_float2(v1.x, v1.y));
        *(__half2*)&o.w = __float22half2_rn(make_float2(v1.z, v1.w));
        ((uint4*)g_cfh)[i] = o;
    }
}

__global__ __launch_bounds__(256, 6) void pair_cov_kernel(
    const int*   __restrict__ x,
    const int*   __restrict__ y,
    const float* __restrict__ stdv,   // [N_COLS, NB_CAT]
    float*       __restrict__ out,
    int n_pairs)
{
    const int lane = threadIdx.x & 31;
    const int sub  = lane & 3;        // 8B chunk of the 32B fp16 row
    const int unit = lane >> 2;       // pair slot (0..7) within warp-iter

    const int warp_global = (int)((blockIdx.x * blockDim.x + threadIdx.x) >> 5);
    const int nwarps      = (int)((gridDim.x * blockDim.x) >> 5);

    const uint2* cfh = (const uint2*)g_cfh;   // row r -> cfh[r*4 + sub]

    int base = warp_global * 8;
    if (base >= n_pairs) return;

    // Prime the index pipeline
    int4 xi = __ldcg((const int4*)x + base + unit);
    int4 yi = __ldcg((const int4*)y + base + unit);

    while (base < n_pairs) {
        const int nbase = base + nwarps * 8;

        // ---- Issue all 8 row gathers back-to-back (MLP = 8), .ca default ----
        uint2 av0 = cfh[(size_t)(0 * NB_CAT + xi.x) * 4 + sub];
        uint2 bv0 = cfh[(size_t)(0 * NB_CAT + yi.x) * 4 + sub];
        uint2 av1 = cfh[(size_t)(1 * NB_CAT + xi.y) * 4 + sub];
        uint2 bv1 = cfh[(size_t)(1 * NB_CAT + yi.y) * 4 + sub];
        uint2 av2 = cfh[(size_t)(2 * NB_CAT + xi.z) * 4 + sub];
        uint2 bv2 = cfh[(size_t)(2 * NB_CAT + yi.z) * 4 + sub];
        uint2 av3 = cfh[(size_t)(3 * NB_CAT + xi.w) * 4 + sub];
        uint2 bv3 = cfh[(size_t)(3 * NB_CAT + yi.w) * 4 + sub];

        // ---- Diagonal term while gathers fly (fp32 std, exact) ----
        float acc = 0.0f;
        {
            const int xd = (sub == 0) ? xi.x : (sub == 1) ? xi.y : (sub == 2) ? xi.z : xi.w;
            const int yd = (sub == 0) ? yi.x : (sub == 1) ? yi.y : (sub == 2) ? yi.z : yi.w;
            if (xd == yd) {
                const float s = stdv[sub * NB_CAT + xd];
                acc = s * s;
            }
        }

        // ---- Prefetch next iteration's indices ----
        int4 nxi, nyi;
        if (nbase < n_pairs) {
            nxi = __ldcg((const int4*)x + nbase + unit);
            nyi = __ldcg((const int4*)y + nbase + unit);
        }
        xi = nxi;
        yi = nyi;

        // ---- Math: per-column dot in half2, fp32 cross-column accumulate ----
        __half2 p0 = __hmul2(*(const __half2*)&av0.x, *(const __half2*)&bv0.x);
        p0 = __hfma2(*(const __half2*)&av0.y, *(const __half2*)&bv0.y, p0);
        __half2 p1 = __hmul2(*(const __half2*)&av1.x, *(const __half2*)&bv1.x);
        p1 = __hfma2(*(const __half2*)&av1.y, *(const __half2*)&bv1.y, p1);
        __half2 p2 = __hmul2(*(const __half2*)&av2.x, *(const __half2*)&bv2.x);
        p2 = __hfma2(*(const __half2*)&av2.y, *(const __half2*)&bv2.y, p2);
        __half2 p3 = __hmul2(*(const __half2*)&av3.x, *(const __half2*)&bv3.x);
        p3 = __hfma2(*(const __half2*)&av3.y, *(const __half2*)&bv3.y, p3);

        const float2 f0 = __half22float2(p0);
        const float2 f1 = __half22float2(p1);
        const float2 f2 = __half22float2(p2);
        const float2 f3 = __half22float2(p3);
        acc += (f0.x + f0.y) + (f1.x + f1.y);
        acc += (f2.x + f2.y) + (f3.x + f3.y);

        // ---- Reduce over the 4 chunk lanes; lane 0 of each unit writes ----
        acc += __shfl_xor_sync(0xffffffffu, acc, 1);
        acc += __shfl_xor_sync(0xffffffffu, acc, 2);

        if (sub == 0) {
            out[base + unit] = acc;   // 8 lanes -> 32 contiguous bytes -> 1 wf
        }

        base = nbase;
    }
}

extern "C" void kernel_launch(void* const* d_in, const int* in_sizes, int n_in,
                              void* d_out, int out_size)
{
    const int*   x    = (const int*)d_in[0];
    const int*   y    = (const int*)d_in[1];
    const float* cf   = (const float*)d_in[2];
    const float* stdv = (const float*)d_in[3];
    float*       out  = (float*)d_out;

    const int n_pairs = out_size;  // 1048576

    // Max L1D: 0% of the unified carveout reserved for shared memory.
    // (Host attribute call; no allocation; deterministic.)
    cudaFuncSetAttribute(pair_cov_kernel,
                         cudaFuncAttributePreferredSharedMemoryCarveout, 0);

    // 1) Convert covar_factor fp32 -> fp16 (vectorized)
    {
        const int n = N_COLS * NB_CAT * RANK / 8;
        convert_cf_kernel<<<(n + 255) / 256, 256>>>(cf);
    }

    // 2) Main gather kernel: single resident wave at 6 blocks/SM
    {
        const int threads = 256;
        const int blocks  = 148 * 6;
        pair_cov_kernel<<<blocks, threads>>>(x, y, stdv, out, n_pairs);
    }
}

// round 16
// speedup vs baseline: 1.3384x; 1.0054x over previous
#include <cuda_runtime.h>
#include <cuda_fp16.h>
#include <cstdint>

#define NB_CAT  8192
#define RANK    16
#define N_COLS  4

// R16 (final): consolidation on the best-measured configuration (R11, total
// 35.55us) + max-L1 carveout (measured neutral, never harmful).
//
// Converged design, with the evidence trail:
//  - fp16 table in a static device buffer (R5: halves L2 sector traffic,
//    doubles L1-resident fraction; -10%).
//  - 4 lanes per pair x 8B chunks; 1 L1 wavefront per 32B row (optimal).
//  - Double batch: 16 row-gathers issued back-to-back per warp-iter at
//    occ 4 / 64-reg budget; index int4s prefetched one iteration ahead.
//  - half2 dot math (HMUL2+HFMA2), fp32 cross-column + diagonal accumulate.
//  - Direct-gather through L1tex: measured 1.18 cyc/row vs the 1.0 floor;
//    SMEM-crossbar, .cg-bypass, fusion, and affinity schemes all measured
//    or costed worse (R7/R9/R12/R13/R14).

__device__ __half2 g_cfh[N_COLS * NB_CAT * RANK / 2];   // 4 MB, layout = cf

__global__ __launch_bounds__(256) void convert_cf_kernel(const float* __restrict__ cf)
{
    const int i = blockIdx.x * blockDim.x + threadIdx.x;   // uint4 (=8 halves) index
    const int n = N_COLS * NB_CAT * RANK / 8;              // 262,144
    if (i < n) {
        const float4 v0 = __ldcg((const float4*)cf + i * 2);
        const float4 v1 = __ldcg((const float4*)cf + i * 2 + 1);
        uint4 o;
        *(__half2*)&o.x = __float22half2_rn(make_float2(v0.x, v0.y));
        *(__half2*)&o.y = __float22half2_rn(make_float2(v0.z, v0.w));
        *(__half2*)&o.z = __float22half2_rn(make_float2(v1.x, v1.y));
        *(__half2*)&o.w = __float22half2_rn(make_float2(v1.z, v1.w));
        ((uint4*)g_cfh)[i] = o;
    }
}

__device__ __forceinline__ float dot_row_group(
    const uint2& a0, const uint2& b0, const uint2& a1, const uint2& b1,
    const uint2& a2, const uint2& b2, const uint2& a3, const uint2& b3)
{
    __half2 p0 = __hmul2(*(const __half2*)&a0.x, *(const __half2*)&b0.x);
    p0 = __hfma2(*(const __half2*)&a0.y, *(const __half2*)&b0.y, p0);
    __half2 p1 = __hmul2(*(const __half2*)&a1.x, *(const __half2*)&b1.x);
    p1 = __hfma2(*(const __half2*)&a1.y, *(const __half2*)&b1.y, p1);
    __half2 p2 = __hmul2(*(const __half2*)&a2.x, *(const __half2*)&b2.x);
    p2 = __hfma2(*(const __half2*)&a2.y, *(const __half2*)&b2.y, p2);
    __half2 p3 = __hmul2(*(const __half2*)&a3.x, *(const __half2*)&b3.x);
    p3 = __hfma2(*(const __half2*)&a3.y, *(const __half2*)&b3.y, p3);
    const float2 f0 = __half22float2(p0);
    const float2 f1 = __half22float2(p1);
    const float2 f2 = __half22float2(p2);
    const float2 f3 = __half22float2(p3);
    return (f0.x + f0.y) + (f1.x + f1.y) + (f2.x + f2.y) + (f3.x + f3.y);
}

__device__ __forceinline__ float diag_term(
    const int4& xi, const int4& yi, int sub, const float* __restrict__ stdv)
{
    const int xd = (sub == 0) ? xi.x : (sub == 1) ? xi.y : (sub == 2) ? xi.z : xi.w;
    const int yd = (sub == 0) ? yi.x : (sub == 1) ? yi.y : (sub == 2) ? yi.z : yi.w;
    if (xd == yd) {
        const float s = stdv[sub * NB_CAT + xd];
        return s * s;
    }
    return 0.0f;
}

__global__ __launch_bounds__(256, 4) void pair_cov_kernel(
    const int*   __restrict__ x,
    const int*   __restrict__ y,
    const float* __restrict__ stdv,   // [N_COLS, NB_CAT]
    float*       __restrict__ out,
    int n_pairs)
{
    const int lane = threadIdx.x & 31;
    const int sub  = lane & 3;        // 8B chunk of the 32B fp16 row
    const int unit = lane >> 2;       // pair slot (0..7) within group

    const int warp_global = (int)((blockIdx.x * blockDim.x + threadIdx.x) >> 5);
    const int nwarps      = (int)((gridDim.x * blockDim.x) >> 5);

    const uint2* cfh = (const uint2*)g_cfh;   // row r -> cfh[r*4 + sub]

    int base = warp_global * 16;
    if (base >= n_pairs) return;

    // Prime index pipeline for both groups (A: base+unit, B: base+8+unit)
    int4 xiA = __ldcg((const int4*)x + base + unit);
    int4 yiA = __ldcg((const int4*)y + base + unit);
    int4 xiB = __ldcg((const int4*)x + base + 8 + unit);
    int4 yiB = __ldcg((const int4*)y + base + 8 + unit);

    while (base < n_pairs) {
        const int nbase = base + nwarps * 16;

        // ---- Issue all 16 row gathers back-to-back (MLP = 16) ----
        uint2 aA0 = cfh[(size_t)(0 * NB_CAT + xiA.x) * 4 + sub];
        uint2 bA0 = cfh[(size_t)(0 * NB_CAT + yiA.x) * 4 + sub];
        uint2 aA1 = cfh[(size_t)(1 * NB_CAT + xiA.y) * 4 + sub];
        uint2 bA1 = cfh[(size_t)(1 * NB_CAT + yiA.y) * 4 + sub];
        uint2 aA2 = cfh[(size_t)(2 * NB_CAT + xiA.z) * 4 + sub];
        uint2 bA2 = cfh[(size_t)(2 * NB_CAT + yiA.z) * 4 + sub];
        uint2 aA3 = cfh[(size_t)(3 * NB_CAT + xiA.w) * 4 + sub];
        uint2 bA3 = cfh[(size_t)(3 * NB_CAT + yiA.w) * 4 + sub];
        uint2 aB0 = cfh[(size_t)(0 * NB_CAT + xiB.x) * 4 + sub];
        uint2 bB0 = cfh[(size_t)(0 * NB_CAT + yiB.x) * 4 + sub];
        uint2 aB1 = cfh[(size_t)(1 * NB_CAT + xiB.y) * 4 + sub];
        uint2 bB1 = cfh[(size_t)(1 * NB_CAT + yiB.y) * 4 + sub];
        uint2 aB2 = cfh[(size_t)(2 * NB_CAT + xiB.z) * 4 + sub];
        uint2 bB2 = cfh[(size_t)(2 * NB_CAT + yiB.z) * 4 + sub];
        uint2 aB3 = cfh[(size_t)(3 * NB_CAT + xiB.w) * 4 + sub];
        uint2 bB3 = cfh[(size_t)(3 * NB_CAT + yiB.w) * 4 + sub];

        // ---- Diagonal terms while gathers fly (fp32 std, exact) ----
        float accA = diag_term(xiA, yiA, sub, stdv);
        float accB = diag_term(xiB, yiB, sub, stdv);

        // ---- Prefetch next iteration's indices ----
        if (nbase < n_pairs) {
            xiA = __ldcg((const int4*)x + nbase + unit);
            yiA = __ldcg((const int4*)y + nbase + unit);
            xiB = __ldcg((const int4*)x + nbase + 8 + unit);
            yiB = __ldcg((const int4*)y + nbase + 8 + unit);
        }

        // ---- Math: half2 dots, fp32 accumulate ----
        accA += dot_row_group(aA0, bA0, aA1, bA1, aA2, bA2, aA3, bA3);
        accB += dot_row_group(aB0, bB0, aB1, bB1, aB2, bB2, aB3, bB3);

        // ---- Reduce over the 4 chunk lanes; lane 0 of each unit writes ----
        accA += __shfl_xor_sync(0xffffffffu, accA, 1);
        accA += __shfl_xor_sync(0xffffffffu, accA, 2);
        accB += __shfl_xor_sync(0xffffffffu, accB, 1);
        accB += __shfl_xor_sync(0xffffffffu, accB, 2);

        if (sub == 0) {
            out[base + unit]     = accA;   // 8 lanes -> 32B -> 1 wf
            out[base + 8 + unit] = accB;   // 8 lanes -> 32B -> 1 wf
        }

        base = nbase;
    }
}

extern "C" void kernel_launch(void* const* d_in, const int* in_sizes, int n_in,
                              void* d_out, int out_size)
{
    const int*   x    = (const int*)d_in[0];
    const int*   y    = (const int*)d_in[1];
    const float* cf   = (const float*)d_in[2];
    const float* stdv = (const float*)d_in[3];
    float*       out  = (float*)d_out;

    const int n_pairs = out_size;  // 1048576

    // Max L1D carveout (0% shared). Measured neutral, never harmful.
    cudaFuncSetAttribute(pair_cov_kernel,
                         cudaFuncAttributePreferredSharedMemoryCarveout, 0);

    // 1) Convert covar_factor fp32 -> fp16 (vectorized)
    {
        const int n = N_COLS * NB_CAT * RANK / 8;
        convert_cf_kernel<<<(n + 255) / 256, 256>>>(cf);
    }

    // 2) Main gather kernel: single resident wave at 4 blocks/SM
    {
        const int threads = 256;
        const int blocks  = 148 * 4;
        pair_cov_kernel<<<blocks, threads>>>(x, y, stdv, out, n_pairs);
    }
}

// round 17
// speedup vs baseline: 1.3469x; 1.0063x over previous
#include <cuda_runtime.h>
#include <cuda_fp16.h>
#include <cstdint>

#define NB_CAT  8192
#define RANK    16
#define N_COLS  4

// R17: same wavefront budget as the R11/R16 champion (1 wf per 32B fp16 row,
// 16 pairs and 128 in-flight wavefronts per warp-iter), but each pair-row is
// now loaded by 2 lanes x uint4 (LDG.128, 16 distinct lines/instr) instead of
// 4 lanes x uint2. This HALVES instructions at constant wavefronts:
//   LDG: 8 per 16 pairs (was 16), SHFL: 1 per pair-reduce (was 2),
//   idx loads: 2 int4-instr streams (was 4).
// R4 showed more-instructions-at-constant-wf regresses; this tests the
// converse. Numerics: 8-element half2 dot chain proven in R13 (1.3e-4).

__device__ __half2 g_cfh[N_COLS * NB_CAT * RANK / 2];   // 4 MB, layout = cf

__global__ __launch_bounds__(256) void convert_cf_kernel(const float* __restrict__ cf)
{
    const int i = blockIdx.x * blockDim.x + threadIdx.x;   // uint4 (=8 halves) index
    const int n = N_COLS * NB_CAT * RANK / 8;              // 262,144
    if (i < n) {
        const float4 v0 = __ldcg((const float4*)cf + i * 2);
        const float4 v1 = __ldcg((const float4*)cf + i * 2 + 1);
        uint4 o;
        *(__half2*)&o.x = __float22half2_rn(make_float2(v0.x, v0.y));
        *(__half2*)&o.y = __float22half2_rn(make_float2(v0.z, v0.w));
        *(__half2*)&o.z = __float22half2_rn(make_float2(v1.x, v1.y));
        *(__half2*)&o.w = __float22half2_rn(make_float2(v1.z, v1.w));
        ((uint4*)g_cfh)[i] = o;
    }
}

// 16B x 16B half2 dot -> fp32 (8 half-pairs; chain proven in R13)
__device__ __forceinline__ float dot16B(const uint4& a, const uint4& b)
{
    __half2 s = __hmul2(*(const __half2*)&a.x, *(const __half2*)&b.x);
    s = __hfma2(*(const __half2*)&a.y, *(const __half2*)&b.y, s);
    s = __hfma2(*(const __half2*)&a.z, *(const __half2*)&b.z, s);
    s = __hfma2(*(const __half2*)&a.w, *(const __half2*)&b.w, s);
    const float2 f = __half22float2(s);
    return f.x + f.y;
}

__global__ __launch_bounds__(256, 4) void pair_cov_kernel(
    const int*   __restrict__ x,
    const int*   __restrict__ y,
    const float* __restrict__ stdv,   // [N_COLS, NB_CAT]
    float*       __restrict__ out,
    int n_pairs)
{
    const int lane = threadIdx.x & 31;
    const int sub  = lane & 1;        // 16B chunk of the 32B fp16 row
    const int unit = lane >> 1;       // pair slot (0..15) within warp-iter

    const int warp_global = (int)((blockIdx.x * blockDim.x + threadIdx.x) >> 5);
    const int nwarps      = (int)((gridDim.x * blockDim.x) >> 5);

    const uint4* cfh4 = (const uint4*)g_cfh;   // row r -> cfh4[r*2 + sub]

    int base = warp_global * 16;
    if (base >= n_pairs) return;

    // Prime the index pipeline (2 lanes per unit load the same int4: broadcast)
    int4 xi = __ldcg((const int4*)x + base + unit);
    int4 yi = __ldcg((const int4*)y + base + unit);

    while (base < n_pairs) {
        const int nbase = base + nwarps * 16;

        // ---- Issue all 8 row gathers back-to-back (16 lines each) ----
        uint4 a0 = cfh4[(size_t)(0 * NB_CAT + xi.x) * 2 + sub];
        uint4 b0 = cfh4[(size_t)(0 * NB_CAT + yi.x) * 2 + sub];
        uint4 a1 = cfh4[(size_t)(1 * NB_CAT + xi.y) * 2 + sub];
        uint4 b1 = cfh4[(size_t)(1 * NB_CAT + yi.y) * 2 + sub];
        uint4 a2 = cfh4[(size_t)(2 * NB_CAT + xi.z) * 2 + sub];
        uint4 b2 = cfh4[(size_t)(2 * NB_CAT + yi.z) * 2 + sub];
        uint4 a3 = cfh4[(size_t)(3 * NB_CAT + xi.w) * 2 + sub];
        uint4 b3 = cfh4[(size_t)(3 * NB_CAT + yi.w) * 2 + sub];

        // ---- Diagonal terms while gathers fly (fp32 std, exact).
        //      Lane sub handles columns {sub, sub+2} (each column once). ----
        float acc = 0.0f;
        {
            const int xd0 = (sub == 0) ? xi.x : xi.y;   // col sub
            const int yd0 = (sub == 0) ? yi.x : yi.y;
            const int xd1 = (sub == 0) ? xi.z : xi.w;   // col sub+2
            const int yd1 = (sub == 0) ? yi.z : yi.w;
            if (xd0 == yd0) {
                const float s = stdv[sub * NB_CAT + xd0];
                acc += s * s;
            }
            if (xd1 == yd1) {
                const float s = stdv[(sub + 2) * NB_CAT + xd1];
                acc += s * s;
            }
        }

        // ---- Prefetch next iteration's indices ----
        int4 nxi, nyi;
        if (nbase < n_pairs) {
            nxi = __ldcg((const int4*)x + nbase + unit);
            nyi = __ldcg((const int4*)y + nbase + unit);
        }
        xi = nxi;
        yi = nyi;

        // ---- Math: per-column 8-element half2 dots, fp32 accumulate ----
        acc += dot16B(a0, b0);
        acc += dot16B(a1, b1);
        acc += dot16B(a2, b2);
        acc += dot16B(a3, b3);

        // ---- Reduce over the 2 chunk lanes; sub==0 lane writes ----
        acc += __shfl_xor_sync(0xffffffffu, acc, 1);

        if (sub == 0) {
            out[base + unit] = acc;   // 16 lanes -> 64 contiguous bytes -> 1 wf
        }

        base = nbase;
    }
}

extern "C" void kernel_launch(void* const* d_in, const int* in_sizes, int n_in,
                              void* d_out, int out_size)
{
    const int*   x    = (const int*)d_in[0];
    const int*   y    = (const int*)d_in[1];
    const float* cf   = (const float*)d_in[2];
    const float* stdv = (const float*)d_in[3];
    float*       out  = (float*)d_out;

    const int n_pairs = out_size;  // 1048576

    // Max L1D carveout (0% shared). Measured neutral, never harmful.
    cudaFuncSetAttribute(pair_cov_kernel,
                         cudaFuncAttributePreferredSharedMemoryCarveout, 0);

    // 1) Convert covar_factor fp32 -> fp16 (vectorized)
    {
        const int n = N_COLS * NB_CAT * RANK / 8;
        convert_cf_kernel<<<(n + 255) / 256, 256>>>(cf);
    }

    // 2) Main gather kernel: single resident wave at 4 blocks/SM
    {
        const int threads = 256;
        const int blocks  = 148 * 4;
        pair_cov_kernel<<<blocks, threads>>>(x, y, stdv, out, n_pairs);
    }
}